// round 6
// baseline (speedup 1.0000x reference)
#include <cuda_runtime.h>
#include <cuda_fp16.h>

// ---------------------------------------------------------------------------
// MSDeformAttention  (bs=8, Lq=Lv=5440, D=256, 8 heads x 32, 4 levels x 4 pts)
//
//   1) V    = value @ Wv + bv        (tf32 MMA, epilogue -> fp16 [b][h][pos][32])
//   2) OFF  = query @ Woff + boff    (tf32 MMA)
//   3) AWL  = query @ Wa + ba        (tf32 MMA, N=128)
//   4) AW   = softmax16(softmax128(AWL))
//   5) MID  = bilinear-gather (fp16 V) + weighted sum   (warp per (b,q,h))
//   6) out  = MID @ Wout + bout      (tf32 MMA)
// ---------------------------------------------------------------------------

#define LQ     5440
#define BSZ    8
#define NH     8
#define DH     32
#define DMODEL 256
#define MROWS  (BSZ * LQ)          // 43520
#define KDIM   256

// scratch (static device globals: allocation-free)
__device__ __half g_Vh [BSZ * NH * LQ * DH];    // [b][h][pos][c]  fp16
__device__ float  g_off[(size_t)MROWS * DMODEL];
__device__ float  g_aw [(size_t)MROWS * 128];
__device__ float  g_mid[(size_t)MROWS * DMODEL];

// tf32 round (rna); returns the b32 bit pattern (cvt.rna.tf32 needs .b32 dst).
__device__ __forceinline__ unsigned f2tf32(float x) {
    unsigned y;
    asm("cvt.rna.tf32.f32 %0, %1;" : "=r"(y) : "f"(x));
    return y;
}

// ---------------------------------------------------------------------------
// tf32 tensor-core GEMM: C[M,N] = A[M,256] @ B[256,N] + bias[N]
// Block tile 128x128, BK=16, 256 threads = 8 warps (4m x 2n), warp tile 32x64.
// mode 0: row-major fp32 C.   mode 1: permuted fp16 write into g_Vh.
// ---------------------------------------------------------------------------
__global__ __launch_bounds__(256) void tf32gemm(
    const float* __restrict__ A, const float* __restrict__ B,
    const float* __restrict__ bias, float* __restrict__ C,
    int N, int mode)
{
    __shared__ unsigned As[16][136];   // [k][m]  (tf32 bit patterns)
    __shared__ unsigned Bs[16][136];   // [k][n]

    const int tid  = threadIdx.x;
    const int lane = tid & 31;
    const int warp = tid >> 5;
    const int gid  = lane >> 2;     // 0..7
    const int tig  = lane & 3;      // 0..3
    const int wm   = (warp >> 1) * 32;
    const int wn   = (warp & 1) * 64;

    const int m0 = blockIdx.y * 128;
    const int n0 = blockIdx.x * 128;

    const int la_row = tid >> 1;
    const int la_cg  = (tid & 1) * 8;
    const int lb_row = tid >> 4;
    const int lb_c4  = (tid & 15) * 4;

    const float* Ap = A + (size_t)(m0 + la_row) * KDIM + la_cg;
    const float* Bp = B + (size_t)lb_row * N + n0 + lb_c4;

    float acc[2][8][4];
#pragma unroll
    for (int mt = 0; mt < 2; mt++)
#pragma unroll
        for (int nt = 0; nt < 8; nt++)
#pragma unroll
            for (int r = 0; r < 4; r++) acc[mt][nt][r] = 0.0f;

    for (int k0 = 0; k0 < KDIM; k0 += 16) {
        float4 av0 = *(const float4*)(Ap);
        float4 av1 = *(const float4*)(Ap + 4);
        As[la_cg + 0][la_row] = f2tf32(av0.x);
        As[la_cg + 1][la_row] = f2tf32(av0.y);
        As[la_cg + 2][la_row] = f2tf32(av0.z);
        As[la_cg + 3][la_row] = f2tf32(av0.w);
        As[la_cg + 4][la_row] = f2tf32(av1.x);
        As[la_cg + 5][la_row] = f2tf32(av1.y);
        As[la_cg + 6][la_row] = f2tf32(av1.z);
        As[la_cg + 7][la_row] = f2tf32(av1.w);

        float4 bv0 = *(const float4*)(Bp);
        float4 bv1 = *(const float4*)(Bp + 64);
        Bs[lb_row][lb_c4 + 0]  = f2tf32(bv0.x);
        Bs[lb_row][lb_c4 + 1]  = f2tf32(bv0.y);
        Bs[lb_row][lb_c4 + 2]  = f2tf32(bv0.z);
        Bs[lb_row][lb_c4 + 3]  = f2tf32(bv0.w);
        Bs[lb_row][lb_c4 + 64] = f2tf32(bv1.x);
        Bs[lb_row][lb_c4 + 65] = f2tf32(bv1.y);
        Bs[lb_row][lb_c4 + 66] = f2tf32(bv1.z);
        Bs[lb_row][lb_c4 + 67] = f2tf32(bv1.w);
        __syncthreads();

#pragma unroll
        for (int ks = 0; ks < 16; ks += 8) {
            unsigned a[2][4], b[8][2];
#pragma unroll
            for (int mt = 0; mt < 2; mt++) {
                const int mb = wm + mt * 16;
                a[mt][0] = As[ks + tig    ][mb + gid    ];
                a[mt][1] = As[ks + tig    ][mb + gid + 8];
                a[mt][2] = As[ks + tig + 4][mb + gid    ];
                a[mt][3] = As[ks + tig + 4][mb + gid + 8];
            }
#pragma unroll
            for (int nt = 0; nt < 8; nt++) {
                const int nb = wn + nt * 8 + gid;
                b[nt][0] = Bs[ks + tig    ][nb];
                b[nt][1] = Bs[ks + tig + 4][nb];
            }
#pragma unroll
            for (int mt = 0; mt < 2; mt++)
#pragma unroll
                for (int nt = 0; nt < 8; nt++) {
                    asm volatile(
                        "mma.sync.aligned.m16n8k8.row.col.f32.tf32.tf32.f32 "
                        "{%0,%1,%2,%3}, {%4,%5,%6,%7}, {%8,%9}, {%0,%1,%2,%3};"
                        : "+f"(acc[mt][nt][0]), "+f"(acc[mt][nt][1]),
                          "+f"(acc[mt][nt][2]), "+f"(acc[mt][nt][3])
                        : "r"(a[mt][0]), "r"(a[mt][1]), "r"(a[mt][2]), "r"(a[mt][3]),
                          "r"(b[nt][0]), "r"(b[nt][1]));
                }
        }
        __syncthreads();
        Ap += 16;
        Bp += (size_t)16 * N;
    }

    // epilogue
#pragma unroll
    for (int mt = 0; mt < 2; mt++) {
#pragma unroll
        for (int rr = 0; rr < 2; rr++) {
            const int m = m0 + wm + mt * 16 + gid + rr * 8;
            const int bb  = m / LQ;
            const int pos = m - bb * LQ;
#pragma unroll
            for (int nt = 0; nt < 8; nt++) {
                const int n = n0 + wn + nt * 8 + tig * 2;
                float2 v;
                v.x = acc[mt][nt][rr * 2 + 0] + bias[n];
                v.y = acc[mt][nt][rr * 2 + 1] + bias[n + 1];
                if (mode == 0) {
                    *(float2*)&C[(size_t)m * N + n] = v;
                } else {
                    const int h = n >> 5;
                    const int c = n & 31;   // even
                    __half2 hv = __floats2half2_rn(v.x, v.y);
                    *(__half2*)&g_Vh[(((size_t)(bb * NH + h)) * LQ + pos) * DH + c] = hv;
                }
            }
        }
    }
}

// ---------------------------------------------------------------------------
// Double softmax: softmax over 128 then softmax over each 16-group.
// One warp per row, lane holds 4 consecutive elements.
// ---------------------------------------------------------------------------
__global__ __launch_bounds__(256) void softmax2_kernel(float* __restrict__ buf)
{
    const int warp = threadIdx.x >> 5;
    const int lane = threadIdx.x & 31;
    const int row  = blockIdx.x * 8 + warp;
    float* p = buf + (size_t)row * 128 + lane * 4;

    float4 v = *(const float4*)p;

    float vm = fmaxf(fmaxf(v.x, v.y), fmaxf(v.z, v.w));
#pragma unroll
    for (int o = 16; o; o >>= 1) vm = fmaxf(vm, __shfl_xor_sync(~0u, vm, o));
    float e0 = expf(v.x - vm), e1 = expf(v.y - vm);
    float e2 = expf(v.z - vm), e3 = expf(v.w - vm);
    float s = e0 + e1 + e2 + e3;
#pragma unroll
    for (int o = 16; o; o >>= 1) s += __shfl_xor_sync(~0u, s, o);
    const float inv = 1.0f / s;
    const float t0 = e0 * inv, t1 = e1 * inv, t2 = e2 * inv, t3 = e3 * inv;

    float gm = fmaxf(fmaxf(t0, t1), fmaxf(t2, t3));
    gm = fmaxf(gm, __shfl_xor_sync(~0u, gm, 1));
    gm = fmaxf(gm, __shfl_xor_sync(~0u, gm, 2));
    float f0 = expf(t0 - gm), f1 = expf(t1 - gm);
    float f2 = expf(t2 - gm), f3 = expf(t3 - gm);
    float gs = f0 + f1 + f2 + f3;
    gs += __shfl_xor_sync(~0u, gs, 1);
    gs += __shfl_xor_sync(~0u, gs, 2);
    const float ginv = 1.0f / gs;

    float4 o4;
    o4.x = f0 * ginv; o4.y = f1 * ginv; o4.z = f2 * ginv; o4.w = f3 * ginv;
    *(float4*)p = o4;
}

// ---------------------------------------------------------------------------
// Sampling + aggregation on fp16 V.  Warp h of block bq handles head h of
// query (b,q); lane = channel.  Reference sampler replicated exactly
// (coords in fp32): x = 0.5*((cx+1)*(W-2)), clipped-corner weights.
// ---------------------------------------------------------------------------
__global__ __launch_bounds__(256) void msdeform_sample_kernel(
    const float* __restrict__ refpts)
{
    const int bq   = blockIdx.x;
    const int b    = bq / LQ;
    const int h    = threadIdx.x >> 5;
    const int lane = threadIdx.x & 31;

    const int starts[4] = {0, 4096, 5120, 5376};
    const int sizes [4] = {64, 32, 16, 8};

    const float* offp = g_off + (size_t)bq * 256;
    const float* awp  = g_aw  + (size_t)bq * 128 + h * 16;
    const float* refp = refpts + (size_t)bq * 8;

    float acc = 0.0f;

#pragma unroll
    for (int l = 0; l < 4; l++) {
        const int   S  = sizes[l];
        const float fs = (float)S;
        const __half* img = g_Vh + (((size_t)(b * NH + h)) * LQ + starts[l]) * DH;
        const float rx = refp[l * 2 + 0];
        const float ry = refp[l * 2 + 1];

#pragma unroll
        for (int p = 0; p < 4; p++) {
            const int oi = ((h * 4 + l) * 4 + p) * 2;
            const float ox = offp[oi];
            const float oy = offp[oi + 1];
            const float w  = awp[l * 4 + p];

            const float cx = rx + ox / fs;
            const float cy = ry + oy / fs;
            const float x = 0.5f * ((cx + 1.0f) * (float)(S - 2));
            const float y = 0.5f * ((cy + 1.0f) * (float)(S - 2));

            const int x0 = (int)floorf(x);
            const int y0 = (int)floorf(y);
            const int x0c = min(max(x0, 0),     S - 1);
            const int x1c = min(max(x0 + 1, 0), S - 1);
            const int y0c = min(max(y0, 0),     S - 1);
            const int y1c = min(max(y0 + 1, 0), S - 1);
            const float x0f = (float)x0c, x1f = (float)x1c;
            const float y0f = (float)y0c, y1f = (float)y1c;

            const float wa = (x1f - x) * (y1f - y);
            const float wb = (x1f - x) * (y - y0f);
            const float wc = (x - x0f) * (y1f - y);
            const float wd = (x - x0f) * (y - y0f);

            const float Ia = __half2float(__ldg(&img[(y0c * S + x0c) * DH + lane]));
            const float Ib = __half2float(__ldg(&img[(y1c * S + x0c) * DH + lane]));
            const float Ic = __half2float(__ldg(&img[(y0c * S + x1c) * DH + lane]));
            const float Id = __half2float(__ldg(&img[(y1c * S + x1c) * DH + lane]));

            acc = fmaf(w, fmaf(wa, Ia, fmaf(wb, Ib, fmaf(wc, Ic, wd * Id))), acc);
        }
    }

    g_mid[(size_t)bq * 256 + h * DH + lane] = acc;
}

// ---------------------------------------------------------------------------
// launch
// ---------------------------------------------------------------------------
extern "C" void kernel_launch(void* const* d_in, const int* in_sizes, int n_in,
                              void* d_out, int out_size)
{
    const float* query = (const float*)d_in[0];
    const float* value = (const float*)d_in[1];
    const float* refp  = (const float*)d_in[2];
    const float* Wv    = (const float*)d_in[3];
    const float* bv    = (const float*)d_in[4];
    const float* Woff  = (const float*)d_in[5];
    const float* boff  = (const float*)d_in[6];
    const float* Wa    = (const float*)d_in[7];
    const float* ba    = (const float*)d_in[8];
    const float* Wout  = (const float*)d_in[9];
    const float* bout  = (const float*)d_in[10];
    float* out = (float*)d_out;

    float *pOff, *pAw, *pMid;
    cudaGetSymbolAddress((void**)&pOff, g_off);
    cudaGetSymbolAddress((void**)&pAw,  g_aw);
    cudaGetSymbolAddress((void**)&pMid, g_mid);

    const dim3 gN256(2, MROWS / 128);   // (2, 340)
    const dim3 gN128(1, MROWS / 128);   // (1, 340)

    tf32gemm<<<gN256, 256>>>(value, Wv, bv, /*C unused in mode1*/ pMid, 256, 1);
    tf32gemm<<<gN256, 256>>>(query, Woff, boff, pOff, 256, 0);
    tf32gemm<<<gN128, 256>>>(query, Wa, ba, pAw, 128, 0);
    softmax2_kernel<<<MROWS / 8, 256>>>(pAw);
    msdeform_sample_kernel<<<MROWS, 256>>>(refp);
    tf32gemm<<<gN256, 256>>>(pMid, Wout, bout, out, 256, 0);
}

// round 7
// speedup vs baseline: 1.4185x; 1.4185x over previous
#include <cuda_runtime.h>
#include <cuda_fp16.h>

// ---------------------------------------------------------------------------
// MSDeformAttention  (bs=8, Lq=Lv=5440, D=256, 8 heads x 32, 4 levels x 4 pts)
//
//   1) V    = value @ Wv + bv        (tf32 MMA, epilogue -> fp16 [b][h][pos][32])
//   2) OFF  = query @ Woff + boff    (tf32 MMA)
//   3) AWL  = query @ Wa + ba        (tf32 MMA, N=128)
//   4) AW   = softmax16(softmax128(AWL))
//   5) MID  = vectorized bilinear-gather (unit-per-corner, LDG.128) + reduce
//   6) out  = MID @ Wout + bout      (tf32 MMA)
// ---------------------------------------------------------------------------

#define LQ     5440
#define BSZ    8
#define NH     8
#define DH     32
#define DMODEL 256
#define MROWS  (BSZ * LQ)          // 43520
#define KDIM   256

// scratch (static device globals: allocation-free)
__device__ __half g_Vh [BSZ * NH * LQ * DH];    // [b][h][pos][c]  fp16
__device__ float  g_off[(size_t)MROWS * DMODEL];
__device__ float  g_aw [(size_t)MROWS * 128];
__device__ float  g_mid[(size_t)MROWS * DMODEL];

// tf32 round (rna); returns the b32 bit pattern (cvt.rna.tf32 needs .b32 dst).
__device__ __forceinline__ unsigned f2tf32(float x) {
    unsigned y;
    asm("cvt.rna.tf32.f32 %0, %1;" : "=r"(y) : "f"(x));
    return y;
}

// ---------------------------------------------------------------------------
// tf32 tensor-core GEMM (unchanged): C[M,N] = A[M,256] @ B[256,N] + bias[N]
// Block tile 128x128, BK=16, 256 threads = 8 warps (4m x 2n), warp tile 32x64.
// mode 0: row-major fp32 C.   mode 1: permuted fp16 write into g_Vh.
// ---------------------------------------------------------------------------
__global__ __launch_bounds__(256) void tf32gemm(
    const float* __restrict__ A, const float* __restrict__ B,
    const float* __restrict__ bias, float* __restrict__ C,
    int N, int mode)
{
    __shared__ unsigned As[16][136];   // [k][m]  (tf32 bit patterns)
    __shared__ unsigned Bs[16][136];   // [k][n]

    const int tid  = threadIdx.x;
    const int lane = tid & 31;
    const int warp = tid >> 5;
    const int gid  = lane >> 2;     // 0..7
    const int tig  = lane & 3;      // 0..3
    const int wm   = (warp >> 1) * 32;
    const int wn   = (warp & 1) * 64;

    const int m0 = blockIdx.y * 128;
    const int n0 = blockIdx.x * 128;

    const int la_row = tid >> 1;
    const int la_cg  = (tid & 1) * 8;
    const int lb_row = tid >> 4;
    const int lb_c4  = (tid & 15) * 4;

    const float* Ap = A + (size_t)(m0 + la_row) * KDIM + la_cg;
    const float* Bp = B + (size_t)lb_row * N + n0 + lb_c4;

    float acc[2][8][4];
#pragma unroll
    for (int mt = 0; mt < 2; mt++)
#pragma unroll
        for (int nt = 0; nt < 8; nt++)
#pragma unroll
            for (int r = 0; r < 4; r++) acc[mt][nt][r] = 0.0f;

    for (int k0 = 0; k0 < KDIM; k0 += 16) {
        float4 av0 = *(const float4*)(Ap);
        float4 av1 = *(const float4*)(Ap + 4);
        As[la_cg + 0][la_row] = f2tf32(av0.x);
        As[la_cg + 1][la_row] = f2tf32(av0.y);
        As[la_cg + 2][la_row] = f2tf32(av0.z);
        As[la_cg + 3][la_row] = f2tf32(av0.w);
        As[la_cg + 4][la_row] = f2tf32(av1.x);
        As[la_cg + 5][la_row] = f2tf32(av1.y);
        As[la_cg + 6][la_row] = f2tf32(av1.z);
        As[la_cg + 7][la_row] = f2tf32(av1.w);

        float4 bv0 = *(const float4*)(Bp);
        float4 bv1 = *(const float4*)(Bp + 64);
        Bs[lb_row][lb_c4 + 0]  = f2tf32(bv0.x);
        Bs[lb_row][lb_c4 + 1]  = f2tf32(bv0.y);
        Bs[lb_row][lb_c4 + 2]  = f2tf32(bv0.z);
        Bs[lb_row][lb_c4 + 3]  = f2tf32(bv0.w);
        Bs[lb_row][lb_c4 + 64] = f2tf32(bv1.x);
        Bs[lb_row][lb_c4 + 65] = f2tf32(bv1.y);
        Bs[lb_row][lb_c4 + 66] = f2tf32(bv1.z);
        Bs[lb_row][lb_c4 + 67] = f2tf32(bv1.w);
        __syncthreads();

#pragma unroll
        for (int ks = 0; ks < 16; ks += 8) {
            unsigned a[2][4], b[8][2];
#pragma unroll
            for (int mt = 0; mt < 2; mt++) {
                const int mb = wm + mt * 16;
                a[mt][0] = As[ks + tig    ][mb + gid    ];
                a[mt][1] = As[ks + tig    ][mb + gid + 8];
                a[mt][2] = As[ks + tig + 4][mb + gid    ];
                a[mt][3] = As[ks + tig + 4][mb + gid + 8];
            }
#pragma unroll
            for (int nt = 0; nt < 8; nt++) {
                const int nb = wn + nt * 8 + gid;
                b[nt][0] = Bs[ks + tig    ][nb];
                b[nt][1] = Bs[ks + tig + 4][nb];
            }
#pragma unroll
            for (int mt = 0; mt < 2; mt++)
#pragma unroll
                for (int nt = 0; nt < 8; nt++) {
                    asm volatile(
                        "mma.sync.aligned.m16n8k8.row.col.f32.tf32.tf32.f32 "
                        "{%0,%1,%2,%3}, {%4,%5,%6,%7}, {%8,%9}, {%0,%1,%2,%3};"
                        : "+f"(acc[mt][nt][0]), "+f"(acc[mt][nt][1]),
                          "+f"(acc[mt][nt][2]), "+f"(acc[mt][nt][3])
                        : "r"(a[mt][0]), "r"(a[mt][1]), "r"(a[mt][2]), "r"(a[mt][3]),
                          "r"(b[nt][0]), "r"(b[nt][1]));
                }
        }
        __syncthreads();
        Ap += 16;
        Bp += (size_t)16 * N;
    }

    // epilogue
#pragma unroll
    for (int mt = 0; mt < 2; mt++) {
#pragma unroll
        for (int rr = 0; rr < 2; rr++) {
            const int m = m0 + wm + mt * 16 + gid + rr * 8;
            const int bb  = m / LQ;
            const int pos = m - bb * LQ;
#pragma unroll
            for (int nt = 0; nt < 8; nt++) {
                const int n = n0 + wn + nt * 8 + tig * 2;
                float2 v;
                v.x = acc[mt][nt][rr * 2 + 0] + bias[n];
                v.y = acc[mt][nt][rr * 2 + 1] + bias[n + 1];
                if (mode == 0) {
                    *(float2*)&C[(size_t)m * N + n] = v;
                } else {
                    const int h = n >> 5;
                    const int c = n & 31;   // even
                    __half2 hv = __floats2half2_rn(v.x, v.y);
                    *(__half2*)&g_Vh[(((size_t)(bb * NH + h)) * LQ + pos) * DH + c] = hv;
                }
            }
        }
    }
}

// ---------------------------------------------------------------------------
// Double softmax (unchanged).
// ---------------------------------------------------------------------------
__global__ __launch_bounds__(256) void softmax2_kernel(float* __restrict__ buf)
{
    const int warp = threadIdx.x >> 5;
    const int lane = threadIdx.x & 31;
    const int row  = blockIdx.x * 8 + warp;
    float* p = buf + (size_t)row * 128 + lane * 4;

    float4 v = *(const float4*)p;

    float vm = fmaxf(fmaxf(v.x, v.y), fmaxf(v.z, v.w));
#pragma unroll
    for (int o = 16; o; o >>= 1) vm = fmaxf(vm, __shfl_xor_sync(~0u, vm, o));
    float e0 = expf(v.x - vm), e1 = expf(v.y - vm);
    float e2 = expf(v.z - vm), e3 = expf(v.w - vm);
    float s = e0 + e1 + e2 + e3;
#pragma unroll
    for (int o = 16; o; o >>= 1) s += __shfl_xor_sync(~0u, s, o);
    const float inv = 1.0f / s;
    const float t0 = e0 * inv, t1 = e1 * inv, t2 = e2 * inv, t3 = e3 * inv;

    float gm = fmaxf(fmaxf(t0, t1), fmaxf(t2, t3));
    gm = fmaxf(gm, __shfl_xor_sync(~0u, gm, 1));
    gm = fmaxf(gm, __shfl_xor_sync(~0u, gm, 2));
    float f0 = expf(t0 - gm), f1 = expf(t1 - gm);
    float f2 = expf(t2 - gm), f3 = expf(t3 - gm);
    float gs = f0 + f1 + f2 + f3;
    gs += __shfl_xor_sync(~0u, gs, 1);
    gs += __shfl_xor_sync(~0u, gs, 2);
    const float ginv = 1.0f / gs;

    float4 o4;
    o4.x = f0 * ginv; o4.y = f1 * ginv; o4.z = f2 * ginv; o4.w = f3 * ginv;
    *(float4*)p = o4;
}

// ---------------------------------------------------------------------------
// Sampling v2: warp h handles head h of query bq.  Lane = (unit u = lane>>2,
// quarter q = lane&3).  Pass i (0..7): unit u handles (point,corner)
// pc = i*8+u: point pidx = pc>>2 = 2i + (u>>2), corner cidx = pc&3.
// Level l = pidx>>2 = i>>1 is UNIFORM per pass (compile-time after unroll).
// Each lane does one LDG.128 (8 fp16 channels q*8..q*8+7) per pass and
// accumulates cw*val into acc[8]; tail: shfl_xor(4,8,16) reduce, lanes 0-3
// write 32 floats per warp.  Corner math matches the reference exactly.
// ---------------------------------------------------------------------------
__global__ __launch_bounds__(256) void msdeform_sample_kernel(
    const float* __restrict__ refpts)
{
    const int bq   = blockIdx.x;
    const int b    = bq / LQ;
    const int h    = threadIdx.x >> 5;
    const int lane = threadIdx.x & 31;
    const int u    = lane >> 2;       // unit 0..7
    const int q    = lane & 3;        // channel quarter

    const int starts[4] = {0, 4096, 5120, 5376};
    const int sizes [4] = {64, 32, 16, 8};

    const float* offp = g_off + (size_t)bq * 256 + h * 32;  // [pidx*2 + xy]
    const float* awp  = g_aw  + (size_t)bq * 128 + h * 16;  // [pidx]
    const float* refp = refpts + (size_t)bq * 8;
    const __half* vbase = g_Vh + ((size_t)(b * NH + h)) * LQ * DH;

    float acc[8];
#pragma unroll
    for (int j = 0; j < 8; j++) acc[j] = 0.0f;

#pragma unroll
    for (int i = 0; i < 8; i++) {
        const int l     = i >> 1;            // level, uniform per pass
        const int S     = sizes[l];
        const int start = starts[l];
        const float fs  = (float)S;

        const int pidx = i * 2 + (u >> 2);   // point 0..15
        const int cidx = u & 3;              // corner 0..3

        const float rx = refp[l * 2 + 0];
        const float ry = refp[l * 2 + 1];
        const float ox = offp[pidx * 2 + 0];
        const float oy = offp[pidx * 2 + 1];
        const float w  = awp[pidx];

        const float cx = rx + ox / fs;
        const float cy = ry + oy / fs;
        const float x = 0.5f * ((cx + 1.0f) * (float)(S - 2));
        const float y = 0.5f * ((cy + 1.0f) * (float)(S - 2));

        const int x0 = (int)floorf(x);
        const int y0 = (int)floorf(y);
        const int x0c = min(max(x0, 0),     S - 1);
        const int x1c = min(max(x0 + 1, 0), S - 1);
        const int y0c = min(max(y0, 0),     S - 1);
        const int y1c = min(max(y0 + 1, 0), S - 1);
        const float x0f = (float)x0c, x1f = (float)x1c;
        const float y0f = (float)y0c, y1f = (float)y1c;

        // corner select: bit1 of cidx = x side, bit0 = y side
        const int   xi = (cidx & 2) ? x1c : x0c;
        const int   yi = (cidx & 1) ? y1c : y0c;
        const float wx = (cidx & 2) ? (x - x0f) : (x1f - x);
        const float wy = (cidx & 1) ? (y - y0f) : (y1f - y);
        const float cw = w * wx * wy;

        const __half* row = vbase + ((size_t)(start + yi * S + xi)) * DH + q * 8;
        const uint4 hv = __ldg((const uint4*)row);

        const float2 f0 = __half22float2(*(const __half2*)&hv.x);
        const float2 f1 = __half22float2(*(const __half2*)&hv.y);
        const float2 f2 = __half22float2(*(const __half2*)&hv.z);
        const float2 f3 = __half22float2(*(const __half2*)&hv.w);

        acc[0] = fmaf(cw, f0.x, acc[0]);
        acc[1] = fmaf(cw, f0.y, acc[1]);
        acc[2] = fmaf(cw, f1.x, acc[2]);
        acc[3] = fmaf(cw, f1.y, acc[3]);
        acc[4] = fmaf(cw, f2.x, acc[4]);
        acc[5] = fmaf(cw, f2.y, acc[5]);
        acc[6] = fmaf(cw, f3.x, acc[6]);
        acc[7] = fmaf(cw, f3.y, acc[7]);
    }

    // reduce across the 8 lanes sharing this q (lanes q, q+4, ..., q+28)
#pragma unroll
    for (int m = 4; m <= 16; m <<= 1)
#pragma unroll
        for (int j = 0; j < 8; j++)
            acc[j] += __shfl_xor_sync(~0u, acc[j], m);

    if (u == 0) {
        float* dst = g_mid + (size_t)bq * 256 + h * 32 + q * 8;
        float4 o0 = make_float4(acc[0], acc[1], acc[2], acc[3]);
        float4 o1 = make_float4(acc[4], acc[5], acc[6], acc[7]);
        *(float4*)(dst + 0) = o0;
        *(float4*)(dst + 4) = o1;
    }
}

// ---------------------------------------------------------------------------
// launch
// ---------------------------------------------------------------------------
extern "C" void kernel_launch(void* const* d_in, const int* in_sizes, int n_in,
                              void* d_out, int out_size)
{
    const float* query = (const float*)d_in[0];
    const float* value = (const float*)d_in[1];
    const float* refp  = (const float*)d_in[2];
    const float* Wv    = (const float*)d_in[3];
    const float* bv    = (const float*)d_in[4];
    const float* Woff  = (const float*)d_in[5];
    const float* boff  = (const float*)d_in[6];
    const float* Wa    = (const float*)d_in[7];
    const float* ba    = (const float*)d_in[8];
    const float* Wout  = (const float*)d_in[9];
    const float* bout  = (const float*)d_in[10];
    float* out = (float*)d_out;

    float *pOff, *pAw, *pMid;
    cudaGetSymbolAddress((void**)&pOff, g_off);
    cudaGetSymbolAddress((void**)&pAw,  g_aw);
    cudaGetSymbolAddress((void**)&pMid, g_mid);

    const dim3 gN256(2, MROWS / 128);   // (2, 340)
    const dim3 gN128(1, MROWS / 128);   // (1, 340)

    tf32gemm<<<gN256, 256>>>(value, Wv, bv, /*C unused in mode1*/ pMid, 256, 1);
    tf32gemm<<<gN256, 256>>>(query, Woff, boff, pOff, 256, 0);
    tf32gemm<<<gN128, 256>>>(query, Wa, ba, pAw, 128, 0);
    softmax2_kernel<<<MROWS / 8, 256>>>(pAw);
    msdeform_sample_kernel<<<MROWS, 256>>>(refp);
    tf32gemm<<<gN256, 256>>>(pMid, Wout, bout, out, 256, 0);
}